// round 5
// baseline (speedup 1.0000x reference)
#include <cuda_runtime.h>
#include <cstdint>

// DeepInsightEncoding: out[b,h,w,c], c in {stamp, scatter, rowcopy, nd, bars}
// B=512, D=32, H=W=128. Output fp32 [512,128,128,5] = 168 MB -> HBM-write bound.
//
// Two launches (stream-ordered in the captured graph):
//  1) streaming kernel: writes all 5 channels, scatter channel = 0. No di map.
//  2) scatter epilogue: 16384 global atomicAdds into channel 1 (duplicates sum).

#define THREADS 256
#define ROWS_PER_CTA 32
#define GROUPS_PER_CTA (ROWS_PER_CTA * 32)   // 32 cols-groups of 4 per row

__global__ void __launch_bounds__(THREADS, 6)
deepinsight_stream(const float* __restrict__ inputs,   // [512,32]
                   const float* __restrict__ stamp,    // [128,128]
                   float*       __restrict__ out)      // [512,128,128,5]
{
    __shared__ float sx[32];
    __shared__ int   sbarh[32];
    __shared__ char4 sc2b[32];          // col->bar, packed 4 cols per entry
    __shared__ float s_inv_range;

    const int b   = blockIdx.x >> 2;
    const int h0  = (blockIdx.x & 3) * ROWS_PER_CTA;
    const int tid = threadIdx.x;

    if (tid < 32) {
        float v = inputs[b * 32 + tid];
        sx[tid] = v;
        int bh = (int)rintf(v * 128.0f);          // round-half-even == jnp.round
        sbarh[tid] = min(max(bh, 0), 128);

        float mn = v, mx = v;
        #pragma unroll
        for (int o = 16; o; o >>= 1) {
            mn = fminf(mn, __shfl_xor_sync(0xffffffffu, mn, o));
            mx = fmaxf(mx, __shfl_xor_sync(0xffffffffu, mx, o));
        }
        if (tid == 0) s_inv_range = 1.0f / (mx - mn);

        // bar columns: first at 17, stride 3, 32 bars (bar_w=1, gap=2, beg=15)
        char c[4];
        #pragma unroll
        for (int k = 0; k < 4; k++) {
            int w = tid * 4 + k - 17;
            c[k] = (w >= 0 && w <= 93 && (w % 3) == 0) ? (char)(w / 3) : (char)-1;
        }
        sc2b[tid] = make_char4(c[0], c[1], c[2], c[3]);
    }
    __syncthreads();

    const float inv_range = s_inv_range;

    #pragma unroll 4
    for (int g = tid; g < GROUPS_PER_CTA; g += THREADS) {
        const int hl = g >> 5;
        const int h  = h0 + hl;
        const int w4 = (g & 31) << 2;

        const float rc  = sx[h >> 2];                              // rowcopy
        const float ndv = fabsf(rc - sx[w4 >> 2]) * inv_range;     // nd (shared by 4 cols)

        const float4 s4 = *(const float4*)(stamp + h * 128 + w4);
        const char4  bb = sc2b[w4 >> 2];

        float bar0 = (bb.x >= 0 && h < sbarh[(int)bb.x]) ? 1.0f : 0.0f;
        float bar1 = (bb.y >= 0 && h < sbarh[(int)bb.y]) ? 1.0f : 0.0f;
        float bar2 = (bb.z >= 0 && h < sbarh[(int)bb.z]) ? 1.0f : 0.0f;
        float bar3 = (bb.w >= 0 && h < sbarh[(int)bb.w]) ? 1.0f : 0.0f;

        // 4 pixels * 5 channels = 20 floats = 5 aligned float4 stores, di=0
        float4* o = (float4*)(out + ((size_t)(b * 128 + h) * 128 + w4) * 5);
        o[0] = make_float4(s4.x, 0.0f, rc,   ndv);
        o[1] = make_float4(bar0, s4.y, 0.0f, rc);
        o[2] = make_float4(ndv,  bar1, s4.z, 0.0f);
        o[3] = make_float4(rc,   ndv,  bar2, s4.w);
        o[4] = make_float4(0.0f, rc,   ndv,  bar3);
    }
}

__global__ void __launch_bounds__(256)
deepinsight_scatter(const float* __restrict__ inputs,   // [512,32]
                    const int*   __restrict__ coords,   // [32,2]
                    float*       __restrict__ out)      // [512,128,128,5]
{
    const int idx = blockIdx.x * 256 + threadIdx.x;     // b*32 + d, 16384 total
    if (idx >= 512 * 32) return;
    const int b = idx >> 5;
    const int d = idx & 31;
    const int r = coords[2 * d];
    const int c = coords[2 * d + 1];
    atomicAdd(out + ((size_t)(b * 128 + r) * 128 + c) * 5 + 1, inputs[idx]);
}

extern "C" void kernel_launch(void* const* d_in, const int* in_sizes, int n_in,
                              void* d_out, int out_size)
{
    const float* inputs = (const float*)d_in[0];   // [512,32]
    const float* stamp  = (const float*)d_in[1];   // [128,128,1]
    const int*   coords = (const int*)d_in[2];     // [32,2]
    float*       out    = (float*)d_out;           // [512,128,128,5]

    deepinsight_stream<<<512 * 4, THREADS>>>(inputs, stamp, out);
    deepinsight_scatter<<<(512 * 32) / 256, 256>>>(inputs, coords, out);
}

// round 9
// speedup vs baseline: 2.2985x; 2.2985x over previous
#include <cuda_runtime.h>
#include <cstdint>

// DeepInsightEncoding: out[b,h,w,c], c in {stamp, scatter, rowcopy, nd, bars}
// B=512, D=32, H=W=128. Output fp32 [512,128,128,5] = 168 MB -> HBM-write bound.
//
// R5: fix L1 store amplification. Pixel-major compute -> per-warp smem staging
// (conflict-free STS) -> coalesced 512B STG.128 drains. Scatter fused via 8KB
// smem di-map (16 rows/CTA).

#define THREADS 256            // 8 warps
#define ROWS_PER_CTA 16
#define NWARPS 8
#define ROW_F4 160             // 128 px * 5 ch / 4 = 160 float4 per row

__global__ void __launch_bounds__(THREADS)
deepinsight_kernel(const float* __restrict__ inputs,   // [512,32]
                   const float* __restrict__ stamp,    // [128,128]
                   const int*   __restrict__ coords,   // [32,2]
                   float*       __restrict__ out)      // [512,128,128,5]
{
    __shared__ float  di[ROWS_PER_CTA * 128];     // 8 KB scatter map
    __shared__ float  stage[NWARPS][ROW_F4 * 4];  // 20 KB: one row per warp
    __shared__ float  sx[32];
    __shared__ int    sbarh[32];
    __shared__ char4  sc2b[32];
    __shared__ float  s_inv_range;

    const int b    = blockIdx.x >> 3;
    const int h0   = (blockIdx.x & 7) * ROWS_PER_CTA;
    const int tid  = threadIdx.x;
    const int warp = tid >> 5;
    const int lane = tid & 31;

    // per-batch scalars
    if (tid < 32) {
        float v = inputs[b * 32 + tid];
        sx[tid] = v;
        int bh = (int)rintf(v * 128.0f);          // round-half-even == jnp.round
        sbarh[tid] = min(max(bh, 0), 128);

        float mn = v, mx = v;
        #pragma unroll
        for (int o = 16; o; o >>= 1) {
            mn = fminf(mn, __shfl_xor_sync(0xffffffffu, mn, o));
            mx = fmaxf(mx, __shfl_xor_sync(0xffffffffu, mx, o));
        }
        if (tid == 0) s_inv_range = 1.0f / (mx - mn);

        // bar columns: first at 17, stride 3, 32 bars (bar_w=1, gap=2, beg=15)
        char c[4];
        #pragma unroll
        for (int k = 0; k < 4; k++) {
            int w = tid * 4 + k - 17;
            c[k] = (w >= 0 && w <= 93 && (w % 3) == 0) ? (char)(w / 3) : (char)-1;
        }
        sc2b[tid] = make_char4(c[0], c[1], c[2], c[3]);
    }
    // zero di map: 2048 floats = 512 float4
    {
        float4* di4 = (float4*)di;
        #pragma unroll
        for (int i = tid; i < (ROWS_PER_CTA * 128) / 4; i += THREADS)
            di4[i] = make_float4(0.f, 0.f, 0.f, 0.f);
    }
    __syncthreads();

    // scatter into smem map (duplicates sum)
    if (tid < 32) {
        int r = coords[2 * tid];
        int c = coords[2 * tid + 1];
        if (r >= h0 && r < h0 + ROWS_PER_CTA)
            atomicAdd(&di[(r - h0) * 128 + c], sx[tid]);
    }
    __syncthreads();

    const float inv_range = s_inv_range;
    float4* const stg = (float4*)stage[warp];

    // each warp: 2 rows (warp, warp+8)
    #pragma unroll
    for (int rr = 0; rr < ROWS_PER_CTA / NWARPS; rr++) {
        const int hl = warp + rr * NWARPS;
        const int h  = h0 + hl;
        const int w4 = lane << 2;

        // ---- fill: pixel-major compute of this lane's 4 pixels ----
        const float rc  = sx[h >> 2];
        const float ndv = fabsf(rc - sx[lane]) * inv_range;   // w4>>2 == lane

        const float4 s4 = __ldg((const float4*)(stamp + h * 128 + w4));
        const float4 d4 = *(const float4*)(&di[hl * 128 + w4]);
        const char4  bb = sc2b[lane];

        const float bar0 = (bb.x >= 0 && h < sbarh[(int)bb.x]) ? 1.0f : 0.0f;
        const float bar1 = (bb.y >= 0 && h < sbarh[(int)bb.y]) ? 1.0f : 0.0f;
        const float bar2 = (bb.z >= 0 && h < sbarh[(int)bb.z]) ? 1.0f : 0.0f;
        const float bar3 = (bb.w >= 0 && h < sbarh[(int)bb.w]) ? 1.0f : 0.0f;

        // 20 floats -> staging (STS.128 @ 80B lane stride: bank conflict-free)
        stg[lane * 5 + 0] = make_float4(s4.x, d4.x, rc,   ndv);
        stg[lane * 5 + 1] = make_float4(bar0, s4.y, d4.y, rc);
        stg[lane * 5 + 2] = make_float4(ndv,  bar1, s4.z, d4.z);
        stg[lane * 5 + 3] = make_float4(rc,   ndv,  bar2, s4.w);
        stg[lane * 5 + 4] = make_float4(d4.w, rc,   ndv,  bar3);
        __syncwarp();

        // ---- drain: fully coalesced 512B stores ----
        float4* orow = (float4*)(out + ((size_t)(b * 128 + h) * 128) * 5);
        #pragma unroll
        for (int j = 0; j < 5; j++)
            orow[j * 32 + lane] = stg[j * 32 + lane];
        __syncwarp();   // staging reused next row
    }
}

extern "C" void kernel_launch(void* const* d_in, const int* in_sizes, int n_in,
                              void* d_out, int out_size)
{
    const float* inputs = (const float*)d_in[0];   // [512,32]
    const float* stamp  = (const float*)d_in[1];   // [128,128,1]
    const int*   coords = (const int*)d_in[2];     // [32,2]
    float*       out    = (float*)d_out;           // [512,128,128,5]

    deepinsight_kernel<<<512 * 8, THREADS>>>(inputs, stamp, coords, out);
}

// round 10
// speedup vs baseline: 2.4626x; 1.0714x over previous
#include <cuda_runtime.h>
#include <cstdint>

// DeepInsightEncoding: out[b,h,w,c], c in {stamp, scatter, rowcopy, nd, bars}
// B=512, D=32, H=W=128. Output fp32 [512,128,128,5] = 168 MB -> HBM-write bound.
//
// R9: keep pixel-major compute + smem row staging, but drain each 2560B row
// with ONE cp.async.bulk (TMA store) instead of 5 LDS.128 + 5 STG.128.
// 512 thr/CTA, one row per warp -> no staging reuse, single wait at exit.

#define THREADS 512            // 16 warps
#define NWARPS 16
#define ROWS_PER_CTA 16
#define ROW_F4 160             // 128 px * 5 ch / 4 = 160 float4 = 2560 B per row

__global__ void __launch_bounds__(THREADS)
deepinsight_kernel(const float* __restrict__ inputs,   // [512,32]
                   const float* __restrict__ stamp,    // [128,128]
                   const int*   __restrict__ coords,   // [32,2]
                   float*       __restrict__ out)      // [512,128,128,5]
{
    __shared__ float  di[ROWS_PER_CTA * 128];            // 8 KB scatter map
    __shared__ __align__(16) float4 stage[NWARPS][ROW_F4]; // 40 KB: one row per warp
    __shared__ float  sx[32];
    __shared__ int    sbarh[32];
    __shared__ char4  sc2b[32];
    __shared__ float  s_inv_range;

    const int b    = blockIdx.x >> 3;
    const int h0   = (blockIdx.x & 7) * ROWS_PER_CTA;
    const int tid  = threadIdx.x;
    const int warp = tid >> 5;
    const int lane = tid & 31;

    // per-batch scalars
    if (tid < 32) {
        float v = inputs[b * 32 + tid];
        sx[tid] = v;
        int bh = (int)rintf(v * 128.0f);          // round-half-even == jnp.round
        sbarh[tid] = min(max(bh, 0), 128);

        float mn = v, mx = v;
        #pragma unroll
        for (int o = 16; o; o >>= 1) {
            mn = fminf(mn, __shfl_xor_sync(0xffffffffu, mn, o));
            mx = fmaxf(mx, __shfl_xor_sync(0xffffffffu, mx, o));
        }
        if (tid == 0) s_inv_range = 1.0f / (mx - mn);

        // bar columns: first at 17, stride 3, 32 bars (bar_w=1, gap=2, beg=15)
        char c[4];
        #pragma unroll
        for (int k = 0; k < 4; k++) {
            int w = tid * 4 + k - 17;
            c[k] = (w >= 0 && w <= 93 && (w % 3) == 0) ? (char)(w / 3) : (char)-1;
        }
        sc2b[tid] = make_char4(c[0], c[1], c[2], c[3]);
    }
    // zero di map: 512 float4 entries, one per thread
    {
        float4* di4 = (float4*)di;
        if (tid < (ROWS_PER_CTA * 128) / 4)
            di4[tid] = make_float4(0.f, 0.f, 0.f, 0.f);
    }
    __syncthreads();

    // scatter into smem map (duplicates sum)
    if (tid < 32) {
        int r = coords[2 * tid];
        int c = coords[2 * tid + 1];
        if (r >= h0 && r < h0 + ROWS_PER_CTA)
            atomicAdd(&di[(r - h0) * 128 + c], sx[tid]);
    }
    __syncthreads();

    const float inv_range = s_inv_range;
    const int   h  = h0 + warp;          // one row per warp
    const int   w4 = lane << 2;

    // ---- fill: pixel-major compute of this lane's 4 pixels ----
    const float rc  = sx[h >> 2];
    const float ndv = fabsf(rc - sx[lane]) * inv_range;   // w4>>2 == lane

    const float4 s4 = __ldg((const float4*)(stamp + h * 128 + w4));
    const float4 d4 = *(const float4*)(&di[warp * 128 + w4]);
    const char4  bb = sc2b[lane];

    const float bar0 = (bb.x >= 0 && h < sbarh[(int)bb.x]) ? 1.0f : 0.0f;
    const float bar1 = (bb.y >= 0 && h < sbarh[(int)bb.y]) ? 1.0f : 0.0f;
    const float bar2 = (bb.z >= 0 && h < sbarh[(int)bb.z]) ? 1.0f : 0.0f;
    const float bar3 = (bb.w >= 0 && h < sbarh[(int)bb.w]) ? 1.0f : 0.0f;

    // 20 floats -> staging (STS.128 @ 80B lane stride: bank conflict-free)
    float4* const stg = stage[warp];
    stg[lane * 5 + 0] = make_float4(s4.x, d4.x, rc,   ndv);
    stg[lane * 5 + 1] = make_float4(bar0, s4.y, d4.y, rc);
    stg[lane * 5 + 2] = make_float4(ndv,  bar1, s4.z, d4.z);
    stg[lane * 5 + 3] = make_float4(rc,   ndv,  bar2, s4.w);
    stg[lane * 5 + 4] = make_float4(d4.w, rc,   ndv,  bar3);
    __syncwarp();

    // ---- drain: single 2560B TMA bulk store, issued by lane 0 ----
    if (lane == 0) {
        uint32_t saddr;
        asm volatile("{ .reg .u64 t; cvta.to.shared.u64 t, %1; cvt.u32.u64 %0, t; }"
                     : "=r"(saddr) : "l"(stg));
        float* gptr = out + (size_t)(b * 128 + h) * 640;   // 128*5 floats/row
        asm volatile("fence.proxy.async.shared::cta;" ::: "memory");
        asm volatile("cp.async.bulk.global.shared::cta.bulk_group [%0], [%1], %2;"
                     :: "l"(gptr), "r"(saddr), "r"(2560u) : "memory");
        asm volatile("cp.async.bulk.commit_group;" ::: "memory");
        // completion before CTA exit (staging not reused, so only wait once)
        asm volatile("cp.async.bulk.wait_group.read 0;" ::: "memory");
    }
}

extern "C" void kernel_launch(void* const* d_in, const int* in_sizes, int n_in,
                              void* d_out, int out_size)
{
    const float* inputs = (const float*)d_in[0];   // [512,32]
    const float* stamp  = (const float*)d_in[1];   // [128,128,1]
    const int*   coords = (const int*)d_in[2];     // [32,2]
    float*       out    = (float*)d_out;           // [512,128,128,5]

    deepinsight_kernel<<<512 * 8, THREADS>>>(inputs, stamp, coords, out);
}